// round 14
// baseline (speedup 1.0000x reference)
#include <cuda_runtime.h>
#include <cuda_fp16.h>
#include <cstdint>

// SwitchingLinear: out[b,:] = W[idx[b]] @ x[b]
// B=2048, C=64, IN=OUT=512 fp32.
// ONE fused kernel. cp.async.cg streams raw fp32 A+B into a 3-slot ring
// (2-stage lookahead, hardware keeps DRAM full). ALL 8 warps compute:
// build fp16 fragments from fp32 smem (LDS.64 + cvt.rn.f16x2, 1 instr/pair),
// single-term m16n8k16 fp16 MMA, fp32 accum (rel_err ~3e-4 < 1e-3).
// Warp = (m-half 32) x (n-quarter 32). 16-row M-skip.
// Rows padded to 160B: LDS.64 verified bank-conflict-free.
// Grid = (expert, n-block 128): 256 CTAs.

#define BB    2048
#define CC    64
#define KIN   512
#define NOUT  512
#define TM    64
#define TN    128
#define KB    32
#define NCH   (KIN / KB)     // 16
#define NSTG  3
#define ROWB  160            // 128B data + 32B pad (bank rotation 8/row)
#define B_OFF (64 * ROWB)    // 10240
#define STGB  (192 * ROWB)   // 30720
#define RING_OFF 1024
#define SMEM_DYN (RING_OFF + NSTG * STGB)   // 93184

__device__ __forceinline__ uint32_t smem_u32(const void* p) {
    uint32_t a;
    asm("{ .reg .u64 t; cvta.to.shared.u64 t, %1; cvt.u32.u64 %0, t; }"
        : "=r"(a) : "l"(p));
    return a;
}

#define CP16(dst, src, sz)                                                   \
    asm volatile("cp.async.cg.shared.global [%0], [%1], 16, %2;"             \
                 :: "r"(dst), "l"(src), "r"(sz))
#define CP_COMMIT() asm volatile("cp.async.commit_group;" ::: "memory")
#define CP_WAIT1()  asm volatile("cp.async.wait_group 1;"  ::: "memory")
#define CP_WAIT0()  asm volatile("cp.async.wait_group 0;"  ::: "memory")

#define LDS64(f0, f1, a)                                                     \
    asm volatile("ld.shared.v2.f32 {%0,%1}, [%2];"                           \
                 : "=f"(f0), "=f"(f1) : "r"(a))

#define MMA(d, a, b0, b1)                                                    \
    asm volatile("mma.sync.aligned.m16n8k16.row.col.f32.f16.f16.f32 "        \
                 "{%0,%1,%2,%3},{%4,%5,%6,%7},{%8,%9},{%0,%1,%2,%3};"        \
                 : "+f"((d)[0]), "+f"((d)[1]), "+f"((d)[2]), "+f"((d)[3])    \
                 : "r"((a)[0]), "r"((a)[1]), "r"((a)[2]), "r"((a)[3]),       \
                   "r"(b0), "r"(b1))

__device__ __forceinline__ uint32_t cvtp(float lo, float hi) {
    uint32_t r;
    asm("cvt.rn.f16x2.f32 %0, %1, %2;" : "=r"(r) : "f"(hi), "f"(lo));
    return r;
}

__global__ __launch_bounds__(256, 2)
void k_all(const float* __restrict__ x, const float* __restrict__ w,
           const int* __restrict__ idx, float* __restrict__ out) {
    extern __shared__ __align__(1024) char sm[];

    int t = threadIdx.x, lane = t & 31, wid = t >> 5;
    int e  = blockIdx.x;
    int n0 = blockIdx.y * TN;

    // ---- phase 0: index dtype detect + ballot compaction ----
    int* s_list = (int*)sm;          // [128], persists below the ring
    int* s_wcnt = (int*)(sm + 512);
    int* s_flag = (int*)(sm + 552);

    if (t == 0) *s_flag = 0;
    __syncthreads();
    if (t < 128 && idx[2 * t + 1]) atomicOr(s_flag, 1);
    __syncthreads();
    const int is64 = (*s_flag == 0);

    uint32_t bal[8];
    int base = wid * 256;
    {
        int c_w = 0;
#pragma unroll
        for (int j = 0; j < 8; j++) {
            int smp = base + j * 32 + lane;
            int c = is64 ? idx[2 * smp] : idx[smp];
            bal[j] = __ballot_sync(0xffffffffu, c == e);
            c_w += __popc(bal[j]);
        }
        if (lane == 0) s_wcnt[wid] = c_w;
    }
    __syncthreads();
    int woff = 0, cnt = 0;
#pragma unroll
    for (int k = 0; k < 8; k++) {
        int v = s_wcnt[k];
        if (k < wid) woff += v;
        cnt += v;
    }
    {
        int run = woff;
#pragma unroll
        for (int j = 0; j < 8; j++) {
            int smp = base + j * 32 + lane;
            if ((bal[j] >> lane) & 1) {
                int pos = run + __popc(bal[j] & ((1u << lane) - 1));
                if (pos < 128) s_list[pos] = smp;
            }
            run += __popc(bal[j]);
        }
    }
    __syncthreads();          // s_list final

    if (cnt == 0) return;     // uniform
    int ntiles = (cnt + TM - 1) / TM;
    if (ntiles > 2) ntiles = 2;

    const float* wc = w + (size_t)e * (NOUT * KIN) + (size_t)n0 * KIN;
    const uint32_t sb = smem_u32(sm) + RING_OFF;

    // Copy mapping: thread t covers row ra = t>>2 (A row; B rows ra, ra+64),
    // float cols (t&3)*8 .. +7 within each 32-float chunk (two 16B pieces).
    const int ra = t >> 2, cq = (t & 3);
    const float* bsrc0 = wc + (size_t)ra * KIN + cq * 8;
    const float* bsrc1 = bsrc0 + (size_t)64 * KIN;
    const uint32_t dA  = (uint32_t)(ra * ROWB + cq * 32);
    const uint32_t dB0 = (uint32_t)(B_OFF + ra * ROWB + cq * 32);

    // Warp tile: m-half wm, n-quarter wn.
    const int wm = wid >> 2, wn = wid & 3;
    const int g = lane >> 2, tt = lane & 3;
    const int nbase = wn * 32;

#pragma unroll 1
    for (int tile = 0; tile < ntiles; tile++) {
        int tb = tile * TM;
        int mcnt = cnt - tb;
        if (mcnt > TM) mcnt = TM;
        const int nmf = (mcnt + 15) >> 4;

        const float* aP = (ra < mcnt)
            ? (x + (size_t)s_list[tb + ra] * KIN + cq * 8) : x;
        const uint32_t asz = (ra < mcnt) ? 16u : 0u;

        // Prologue: issue stages 0, 1.
#pragma unroll
        for (int s = 0; s < 2; s++) {
            uint32_t sl = sb + (uint32_t)s * STGB;
            int k0 = s * KB;
            CP16(sl + dA, aP + k0, asz);
            CP16(sl + dA + 16, aP + k0 + 4, asz);
            CP16(sl + dB0, bsrc0 + k0, 16u);
            CP16(sl + dB0 + 16, bsrc0 + k0 + 4, 16u);
            CP16(sl + dB0 + 64 * ROWB, bsrc1 + k0, 16u);
            CP16(sl + dB0 + 64 * ROWB + 16, bsrc1 + k0 + 4, 16u);
            CP_COMMIT();
        }

        float acc[2][4][4];
#pragma unroll
        for (int i = 0; i < 2; i++)
#pragma unroll
            for (int j = 0; j < 4; j++)
#pragma unroll
                for (int q = 0; q < 4; q++) acc[i][j][q] = 0.f;

        int slot = 0, slot2 = 2;   // compute slot, issue slot
#pragma unroll 1
        for (int s = 0; s < NCH; s++) {
            CP_WAIT1();
            __syncthreads();
            uint32_t bs = sb + (uint32_t)slot * STGB;

#pragma unroll
            for (int ks = 0; ks < 2; ks++) {
                // B fragments: 4 n8 blocks, 2 regs each.
                uint32_t bf[4][2];
#pragma unroll
                for (int p = 0; p < 4; p++) {
                    uint32_t ad = bs + B_OFF
                        + (uint32_t)((nbase + p * 8 + g) * ROWB + ks * 64 + tt * 8);
                    float f0, f1;
                    LDS64(f0, f1, ad);      bf[p][0] = cvtp(f0, f1);
                    LDS64(f0, f1, ad + 32); bf[p][1] = cvtp(f0, f1);
                }
                // A fragments + MMAs per active m-frag.
#pragma unroll
                for (int i = 0; i < 2; i++) {
                    int mf = wm * 2 + i;
                    if (mf < nmf) {
                        uint32_t ah[4];
                        uint32_t ad = bs
                            + (uint32_t)((mf * 16 + g) * ROWB + ks * 64 + tt * 8);
                        float f0, f1;
                        LDS64(f0, f1, ad);                 ah[0] = cvtp(f0, f1);
                        LDS64(f0, f1, ad + 8 * ROWB);      ah[1] = cvtp(f0, f1);
                        LDS64(f0, f1, ad + 32);            ah[2] = cvtp(f0, f1);
                        LDS64(f0, f1, ad + 8 * ROWB + 32); ah[3] = cvtp(f0, f1);
#pragma unroll
                        for (int p = 0; p < 4; p++)
                            MMA(acc[i][p], ah, bf[p][0], bf[p][1]);
                    }
                }
            }

            // Issue stage s+2 into slot2 (== slot s-1, drained by the sync).
            if (s + 2 < NCH) {
                int k0 = (s + 2) * KB;
                uint32_t sl = sb + (uint32_t)slot2 * STGB;
                CP16(sl + dA, aP + k0, asz);
                CP16(sl + dA + 16, aP + k0 + 4, asz);
                CP16(sl + dB0, bsrc0 + k0, 16u);
                CP16(sl + dB0 + 16, bsrc0 + k0 + 4, 16u);
                CP16(sl + dB0 + 64 * ROWB, bsrc1 + k0, 16u);
                CP16(sl + dB0 + 64 * ROWB + 16, bsrc1 + k0 + 4, 16u);
            }
            CP_COMMIT();
            if (++slot == NSTG) slot = 0;
            if (++slot2 == NSTG) slot2 = 0;
        }

        // ---- epilogue ----
#pragma unroll
        for (int i = 0; i < 2; i++) {
            int mf = wm * 2 + i;
            int m0 = mf * 16 + g;
            int m1 = m0 + 8;
            int r0 = (m0 < mcnt) ? s_list[tb + m0] : -1;
            int r1 = (m1 < mcnt) ? s_list[tb + m1] : -1;
#pragma unroll
            for (int p = 0; p < 4; p++) {
                int col = n0 + nbase + p * 8 + tt * 2;
                if (r0 >= 0)
                    *(float2*)(out + (size_t)r0 * NOUT + col) =
                        make_float2(acc[i][p][0], acc[i][p][1]);
                if (r1 >= 0)
                    *(float2*)(out + (size_t)r1 * NOUT + col) =
                        make_float2(acc[i][p][2], acc[i][p][3]);
            }
        }
        if (tile + 1 < ntiles) {
            CP_WAIT0();
            __syncthreads();
        }
    }
}

extern "C" void kernel_launch(void* const* d_in, const int* in_sizes, int n_in,
                              void* d_out, int out_size) {
    const float* x = 0; const int* idx = 0; const float* w = 0;
    for (int i = 0; i < n_in; i++) {
        if (in_sizes[i] == BB)              idx = (const int*)d_in[i];
        else if (in_sizes[i] == BB * KIN)   x   = (const float*)d_in[i];
        else                                w   = (const float*)d_in[i];
    }
    cudaFuncSetAttribute(k_all, cudaFuncAttributeMaxDynamicSharedMemorySize, SMEM_DYN);
    k_all<<<dim3(CC, NOUT / TN), 256, SMEM_DYN>>>(x, w, idx, (float*)d_out);
}

// round 17
// speedup vs baseline: 1.2117x; 1.2117x over previous
#include <cuda_runtime.h>
#include <cuda_fp16.h>
#include <cstdint>

// SwitchingLinear: out[b,:] = W[idx[b]] @ x[b]
// B=2048, C=64, IN=OUT=512 fp32.
// ONE fused kernel, warp-specialized producer/consumer, 4-deep 12KB ring.
// Single-term fp16 HMMA (rel_err ~3e-4 < 1e-3 budget).
//   warps 4-7: producers, REGISTER DOUBLE-BUFFERED: LDGs for stage s+1 are
//              in flight during the whole of stage s's cvt+STS -> DRAM
//              latency pipelined, not serialized.
//   warps 0-3: consumers (LDSM -> m16n8k16 f16 MMA, fp32 accum), M-skip.
// KB=32 (16 stages) so the double buffer fits in registers (2x48 + ~20).
// Grid = (expert, n-block 128): 256 CTAs.

#define BB    2048
#define CC    64
#define KIN   512
#define NOUT  512
#define TM    64
#define TN    128
#define KB    32
#define NCH   (KIN / KB)     // 16
#define NSTG  4
#define STGB  12288          // A 64x64B (4KB) | B 128x64B (8KB)
#define RING_OFF 1024
#define SMEM_DYN (RING_OFF + NSTG * STGB)   // 50176

__device__ __forceinline__ uint32_t smem_u32(const void* p) {
    uint32_t a;
    asm("{ .reg .u64 t; cvta.to.shared.u64 t, %1; cvt.u32.u64 %0, t; }"
        : "=r"(a) : "l"(p));
    return a;
}

#define SW64(o) ((o) ^ (((o) >> 3) & 0x30))

#define BAR_SYNC(id)   asm volatile("bar.sync %0, 256;"   :: "r"(id) : "memory")
#define BAR_ARRIVE(id) asm volatile("bar.arrive %0, 256;" :: "r"(id) : "memory")

#define LDSM4(r0, r1, r2, r3, a)                                             \
    asm volatile("ldmatrix.sync.aligned.m8n8.x4.shared.b16 {%0,%1,%2,%3}, [%4];" \
                 : "=r"(r0), "=r"(r1), "=r"(r2), "=r"(r3) : "r"(a))

#define MMA(d, a, b0, b1)                                                    \
    asm volatile("mma.sync.aligned.m16n8k16.row.col.f32.f16.f16.f32 "        \
                 "{%0,%1,%2,%3},{%4,%5,%6,%7},{%8,%9},{%0,%1,%2,%3};"        \
                 : "+f"((d)[0]), "+f"((d)[1]), "+f"((d)[2]), "+f"((d)[3])    \
                 : "r"((a)[0]), "r"((a)[1]), "r"((a)[2]), "r"((a)[3]),       \
                   "r"(b0), "r"(b1))

__device__ __forceinline__ uint32_t cvtp(float lo, float hi) {
    uint32_t r;
    asm("cvt.rn.f16x2.f32 %0, %1, %2;" : "=r"(r) : "f"(hi), "f"(lo));
    return r;
}

__global__ __launch_bounds__(256, 2)
void k_all(const float* __restrict__ x, const float* __restrict__ w,
           const int* __restrict__ idx, float* __restrict__ out) {
    extern __shared__ __align__(1024) char sm[];

    int t = threadIdx.x, lane = t & 31, wid = t >> 5;
    int e  = blockIdx.x;
    int n0 = blockIdx.y * TN;

    // ---- phase 0: index dtype detect + ballot compaction ----
    int* s_list = (int*)sm;          // [128], persists below the ring
    int* s_wcnt = (int*)(sm + 512);
    int* s_flag = (int*)(sm + 552);

    if (t == 0) *s_flag = 0;
    __syncthreads();
    if (t < 128 && idx[2 * t + 1]) atomicOr(s_flag, 1);
    __syncthreads();
    const int is64 = (*s_flag == 0);

    uint32_t bal[8];
    int base = wid * 256;
    {
        int c_w = 0;
#pragma unroll
        for (int j = 0; j < 8; j++) {
            int smp = base + j * 32 + lane;
            int c = is64 ? idx[2 * smp] : idx[smp];
            bal[j] = __ballot_sync(0xffffffffu, c == e);
            c_w += __popc(bal[j]);
        }
        if (lane == 0) s_wcnt[wid] = c_w;
    }
    __syncthreads();
    int woff = 0, cnt = 0;
#pragma unroll
    for (int k = 0; k < 8; k++) {
        int v = s_wcnt[k];
        if (k < wid) woff += v;
        cnt += v;
    }
    {
        int run = woff;
#pragma unroll
        for (int j = 0; j < 8; j++) {
            int smp = base + j * 32 + lane;
            if ((bal[j] >> lane) & 1) {
                int pos = run + __popc(bal[j] & ((1u << lane) - 1));
                if (pos < 128) s_list[pos] = smp;
            }
            run += __popc(bal[j]);
        }
    }
    __syncthreads();          // s_list final

    if (cnt == 0) return;     // uniform
    int ntiles = (cnt + TM - 1) / TM;
    if (ntiles > 2) ntiles = 2;

    const float* wc = w + (size_t)e * (NOUT * KIN) + (size_t)n0 * KIN;
    const uint32_t sb = smem_u32(sm) + RING_OFF;

    if (t >= 128) {
        // ================= PRODUCER (double-buffered) =================
        int p  = t - 128;
        int rg = p >> 3;                 // 0..15 base row
        int kl = (p & 7) * 4;            // float col 0..28 within 32-chunk
        const float* wb = wc + (size_t)rg * KIN + kl;

        // Store byte offsets (SW64) for rows rg+16j.
        uint32_t soA[4], soB[8];
#pragma unroll
        for (int j = 0; j < 4; j++)
            soA[j] = SW64((uint32_t)((rg + 16 * j) * 64 + (p & 7) * 8));
#pragma unroll
        for (int j = 0; j < 8; j++)
            soB[j] = 4096u + SW64((uint32_t)((rg + 16 * j) * 64 + (p & 7) * 8));

#define P_LOAD(Ab, Bb, k0)                                                    \
        do {                                                                  \
            _Pragma("unroll")                                                 \
            for (int j = 0; j < 4; j++)                                       \
                Ab[j] = app[j] ? *(const float4*)(app[j] + (k0))              \
                               : make_float4(0.f, 0.f, 0.f, 0.f);             \
            _Pragma("unroll")                                                 \
            for (int j = 0; j < 8; j++)                                       \
                Bb[j] = *(const float4*)(wb + (size_t)j * (16 * KIN) + (k0)); \
        } while (0)

#define P_STORE(Ab, Bb, sg)                                                   \
        do {                                                                  \
            if ((sg) >= NSTG) BAR_SYNC(5 + ((sg) & 3));                       \
            char* stg = sm + RING_OFF + ((sg) & 3) * STGB;                    \
            _Pragma("unroll")                                                 \
            for (int j = 0; j < 4; j++)                                       \
                *(uint2*)(stg + soA[j]) =                                     \
                    make_uint2(cvtp(Ab[j].x, Ab[j].y), cvtp(Ab[j].z, Ab[j].w)); \
            _Pragma("unroll")                                                 \
            for (int j = 0; j < 8; j++)                                       \
                *(uint2*)(stg + soB[j]) =                                     \
                    make_uint2(cvtp(Bb[j].x, Bb[j].y), cvtp(Bb[j].z, Bb[j].w)); \
            BAR_ARRIVE(1 + ((sg) & 3));                                       \
        } while (0)

#pragma unroll 1
        for (int tile = 0; tile < ntiles; tile++) {
            int tb = tile * TM;
            int mcnt = cnt - tb;
            if (mcnt > TM) mcnt = TM;
            const float* app[4];
#pragma unroll
            for (int j = 0; j < 4; j++) {
                int r = rg + 16 * j;
                app[j] = (r < mcnt) ? (x + (size_t)s_list[tb + r] * KIN + kl)
                                    : (const float*)0;
            }

            float4 A0[4], B0[8], A1[4], B1[8];
            P_LOAD(A0, B0, 0);                 // stage 0 in flight

#pragma unroll 1
            for (int s = 0; s < NCH; s += 2) {
                int sg0 = tile * NCH + s;
                // Issue s+1 loads, then drain buffer 0 for stage s.
                if (s + 1 < NCH) P_LOAD(A1, B1, (s + 1) * KB);
                P_STORE(A0, B0, sg0);
                // Issue s+2 loads, then drain buffer 1 for stage s+1.
                if (s + 2 < NCH) P_LOAD(A0, B0, (s + 2) * KB);
                P_STORE(A1, B1, sg0 + 1);
            }
        }
    } else {
        // ================= CONSUMER =================
        int cw = wid;                    // 0..3
        int nbase = cw * 32;
        int a_r = (lane & 7) + ((lane >> 3) & 1) * 8;
        int a_c = ((lane >> 4) & 1) * 16;   // bytes (k half)
        int b_r = (lane & 7) + ((lane >> 4) & 1) * 8;
        int b_c = ((lane >> 3) & 1) * 16;   // bytes

#pragma unroll 1
        for (int tile = 0; tile < ntiles; tile++) {
            int tb = tile * TM;
            int mcnt = cnt - tb;
            if (mcnt > TM) mcnt = TM;
            const int nmf = (mcnt + 15) >> 4;   // 1..4

            float acc[4][4][4];
#pragma unroll
            for (int i = 0; i < 4; i++)
#pragma unroll
                for (int j = 0; j < 4; j++)
#pragma unroll
                    for (int q = 0; q < 4; q++) acc[i][j][q] = 0.f;

#pragma unroll 1
            for (int s = 0; s < NCH; s++) {
                int sg = tile * NCH + s;
                BAR_SYNC(1 + (sg & 3));
                uint32_t bs = sb + (uint32_t)((sg & 3) * STGB);
#pragma unroll
                for (int ks = 0; ks < 2; ks++) {     // 2 x k16 per stage
                    uint32_t bh[2][4];
#pragma unroll
                    for (int np = 0; np < 2; np++) {
                        uint32_t o = SW64((uint32_t)((nbase + np * 16 + b_r) * 64 + ks * 32 + b_c));
                        LDSM4(bh[np][0], bh[np][1], bh[np][2], bh[np][3], bs + 4096 + o);
                    }
#pragma unroll
                    for (int mf = 0; mf < 4; mf++) {
                        if (mf < nmf) {
                            uint32_t ah[4];
                            uint32_t o = SW64((uint32_t)((mf * 16 + a_r) * 64 + ks * 32 + a_c));
                            LDSM4(ah[0], ah[1], ah[2], ah[3], bs + o);
#pragma unroll
                            for (int nf = 0; nf < 4; nf++) {
                                int np = nf >> 1, oo = (nf & 1) * 2;
                                MMA(acc[mf][nf], ah, bh[np][oo], bh[np][oo + 1]);
                            }
                        }
                    }
                }
                BAR_ARRIVE(5 + (sg & 3));
            }

            // ---- epilogue ----
#pragma unroll
            for (int mf = 0; mf < 4; mf++) {
                int m0 = mf * 16 + (lane >> 2);
                int m1 = m0 + 8;
                int r0 = (m0 < mcnt) ? s_list[tb + m0] : -1;
                int r1 = (m1 < mcnt) ? s_list[tb + m1] : -1;
#pragma unroll
                for (int nf = 0; nf < 4; nf++) {
                    int col = n0 + nbase + nf * 8 + (lane & 3) * 2;
                    if (r0 >= 0)
                        *(float2*)(out + (size_t)r0 * NOUT + col) =
                            make_float2(acc[mf][nf][0], acc[mf][nf][1]);
                    if (r1 >= 0)
                        *(float2*)(out + (size_t)r1 * NOUT + col) =
                            make_float2(acc[mf][nf][2], acc[mf][nf][3]);
                }
            }
        }
    }
}

extern "C" void kernel_launch(void* const* d_in, const int* in_sizes, int n_in,
                              void* d_out, int out_size) {
    const float* x = 0; const int* idx = 0; const float* w = 0;
    for (int i = 0; i < n_in; i++) {
        if (in_sizes[i] == BB)              idx = (const int*)d_in[i];
        else if (in_sizes[i] == BB * KIN)   x   = (const float*)d_in[i];
        else                                w   = (const float*)d_in[i];
    }
    cudaFuncSetAttribute(k_all, cudaFuncAttributeMaxDynamicSharedMemorySize, SMEM_DYN);
    k_all<<<dim3(CC, NOUT / TN), 256, SMEM_DYN>>>(x, w, idx, (float*)d_out);
}